// round 5
// baseline (speedup 1.0000x reference)
#include <cuda_runtime.h>
#include <math.h>

#define Bx 256
#define Nn 1024
#define Ee 8192
#define FINc 8
#define Hh 4
#define Dd 5
#define HD 20
#define DP 6                  // padded head dim
#define HDP 24                // padded feature count
#define NQP 6                 // padded quads per row
#define ES (Ee + Nn)          // 9216 edges incl. self loops
#define CHK (ES / 1024)       // 9 chunks of 1024 edges
#define AOUTc 64
#define OBSc 1024
#define HIDc 256
#define NOUTc 64
#define NEGs 0.2f
#define EPSbn 1e-5f
#define TOTROWS (Bx * Nn)     // 262144
#define HROWS (3 * TOTROWS)   // quads per head-half plane group

// ---------------- device scratch: padded SoA float4 planes, r = n*Bx + b ----------------
// plane index: half k in {0,1} owns quads [3k, 3k+3); feature j (padded, 0..23)
// maps real f = h*5+d  <->  padded p = h*6+d (pad at d==5, always 0)
__device__ float4 g_xl4[NQP * TOTROWS];
__device__ float4 g_xr4[NQP * TOTROWS];
__device__ float4 g_h4[NQP * TOTROWS];
__device__ float g_pool[Bx * HD];
__device__ float g_bn[4 * HD];       // [sum0(20), sq0(20), sum1(20), sq1(20)]
__device__ int   g_rowptr[Nn + 1];
__device__ int   g_cnt[CHK * Nn];
__device__ int   g_csrc[ES];

// ---------------- helpers ----------------
__device__ __forceinline__ void edge_sd(const int* ei, int e, int& s, int& d) {
    if (e < Ee) { s = ei[e]; d = ei[Ee + e]; }
    else        { s = e - Ee; d = s; }       // appended self loops
}

// ---------------- fused CSR stage 1: zero + per-chunk hist + scan (1 block, 1024 thr) ----
__global__ void k_csr1(const int* __restrict__ ei) {
    __shared__ int run[Nn];
    __shared__ int sc[Nn];
    int t = threadIdx.x;
    if (t < 4 * HD) g_bn[t] = 0.f;
    run[t] = 0;
    __syncthreads();
    #pragma unroll
    for (int c = 0; c < CHK; c++) {
        g_cnt[c * Nn + t] = run[t];          // chunk-exclusive running count
        __syncthreads();
        int e = c * 1024 + t;
        int s, d; edge_sd(ei, e, s, d);
        atomicAdd(&run[d], 1);
        __syncthreads();
    }
    int tot = run[t];
    sc[t] = tot;
    __syncthreads();
    for (int off = 1; off < Nn; off <<= 1) { // Hillis-Steele inclusive scan
        int v = (t >= off) ? sc[t - off] : 0;
        __syncthreads();
        sc[t] += v;
        __syncthreads();
    }
    g_rowptr[t] = sc[t] - tot;               // exclusive
    if (t == Nn - 1) g_rowptr[Nn] = sc[t];
}

// ---------------- CSR scatter: match_any + warp-serialized cursors (deterministic) ----
__global__ void k_scatter(const int* __restrict__ ei) {
    __shared__ int cur[Nn];
    int t = threadIdx.x;                      // 1024
    int chunk = blockIdx.x;                   // 9
    cur[t] = g_rowptr[t] + g_cnt[chunk * Nn + t];
    __syncthreads();
    int e = chunk * 1024 + t;
    int s, d; edge_sd(ei, e, s, d);
    int w = t >> 5, lane = t & 31;
    #pragma unroll 1
    for (int ww = 0; ww < 32; ww++) {         // warps take turns -> stable order
        if (w == ww) {
            unsigned mask = __match_any_sync(0xffffffffu, d);
            int leader = __ffs(mask) - 1;
            int rank = __popc(mask & ((1u << lane) - 1u));
            int base = 0;
            if (lane == leader) base = atomicAdd(&cur[d], __popc(mask));
            base = __shfl_sync(0xffffffffu, base, leader);
            g_csrc[base + rank] = s;
        }
        __syncthreads();
    }
}

// ---------------- layer-0 linear: xl = x@Wl0, xr = x@Wr0  (write padded planes) --------
__global__ void k_lin0(const float* __restrict__ x,
                       const float* __restrict__ Wl, const float* __restrict__ Wr) {
    __shared__ float sl[FINc * HD], sr[FINc * HD];
    int t = threadIdx.x;
    if (t < FINc * HD) { sl[t] = Wl[t]; sr[t] = Wr[t]; }
    __syncthreads();
    int r = blockIdx.x * blockDim.x + t;     // r = n*Bx + b
    int n = r >> 8;
    int b = r & (Bx - 1);
    const float4* xp = (const float4*)(x + (b * Nn + n) * FINc);
    float4 v0 = xp[0], v1 = xp[1];
    float xv[FINc] = {v0.x, v0.y, v0.z, v0.w, v1.x, v1.y, v1.z, v1.w};
    float al[HDP], ar[HDP];
    #pragma unroll
    for (int j = 0; j < HDP; j++) {
        int h = j / DP, d = j % DP;
        if (d < Dd) {
            int o = h * Dd + d;
            float a = 0.f, c = 0.f;
            #pragma unroll
            for (int i = 0; i < FINc; i++) {
                a = fmaf(xv[i], sl[i * HD + o], a);
                c = fmaf(xv[i], sr[i * HD + o], c);
            }
            al[j] = a; ar[j] = c;
        } else { al[j] = 0.f; ar[j] = 0.f; }
    }
    #pragma unroll
    for (int q = 0; q < NQP; q++) {
        g_xl4[q * TOTROWS + r] = make_float4(al[q*4], al[q*4+1], al[q*4+2], al[q*4+3]);
        g_xr4[q * TOTROWS + r] = make_float4(ar[q*4], ar[q*4+1], ar[q*4+2], ar[q*4+3]);
    }
}

// ---------------- layer-1 linear with fused BN0 affine (padded planes in/out) ----------
__global__ void k_lin1(const float* __restrict__ Wl, const float* __restrict__ Wr,
                       const float* __restrict__ gam, const float* __restrict__ bet) {
    __shared__ float sl[HD * HD], sr[HD * HD], sa[HD], sc_[HD];
    int t = threadIdx.x;
    if (t < HD) {
        float mu  = g_bn[t] * (1.f / TOTROWS);
        float var = g_bn[HD + t] * (1.f / TOTROWS) - mu * mu;
        float a = gam[t] * rsqrtf(var + EPSbn);
        sa[t] = a;
        sc_[t] = bet[t] - mu * a;
    }
    for (int i = t; i < HD * HD; i += blockDim.x) { sl[i] = Wl[i]; sr[i] = Wr[i]; }
    __syncthreads();
    int r = blockIdx.x * blockDim.x + t;
    float hp[HDP];
    #pragma unroll
    for (int q = 0; q < NQP; q++) {
        float4 h4 = g_h4[q * TOTROWS + r];
        hp[q*4+0] = h4.x; hp[q*4+1] = h4.y; hp[q*4+2] = h4.z; hp[q*4+3] = h4.w;
    }
    float v[HD];
    #pragma unroll
    for (int f = 0; f < HD; f++)
        v[f] = fmaf(hp[(f / Dd) * DP + (f % Dd)], sa[f], sc_[f]);
    float al[HDP], ar[HDP];
    #pragma unroll
    for (int j = 0; j < HDP; j++) {
        int h = j / DP, d = j % DP;
        if (d < Dd) {
            int o = h * Dd + d;
            float a = 0.f, c = 0.f;
            #pragma unroll
            for (int i = 0; i < HD; i++) {
                a = fmaf(v[i], sl[i * HD + o], a);
                c = fmaf(v[i], sr[i * HD + o], c);
            }
            al[j] = a; ar[j] = c;
        } else { al[j] = 0.f; ar[j] = 0.f; }
    }
    #pragma unroll
    for (int q = 0; q < NQP; q++) {
        g_xl4[q * TOTROWS + r] = make_float4(al[q*4], al[q*4+1], al[q*4+2], al[q*4+3]);
        g_xr4[q * TOTROWS + r] = make_float4(ar[q*4], ar[q*4+1], ar[q*4+2], ar[q*4+3]);
    }
}

// ---------------- GATv2 aggregation: block = (node, head-half), thread = batch --------
// Per-thread state halved vs R4 -> 4 blocks/SM occupancy. Fused BN stats.
__device__ __forceinline__ void gat_edge12(const float xl[12], const float xr[12],
                                           const float* sat,
                                           float& s0, float& s1, float acc[12]) {
    float e0 = 0.f, e1 = 0.f;
    #pragma unroll
    for (int d = 0; d < DP; d++) {
        float v0 = xl[d] + xr[d];
        v0 = fmaxf(v0, NEGs * v0);
        e0 = fmaf(v0, sat[d], e0);
        float v1 = xl[DP + d] + xr[DP + d];
        v1 = fmaxf(v1, NEGs * v1);
        e1 = fmaf(v1, sat[DP + d], e1);
    }
    float w0 = __expf(e0), w1 = __expf(e1);   // |e| = O(1): no max-subtract needed
    s0 += w0; s1 += w1;
    #pragma unroll
    for (int d = 0; d < DP; d++) {
        acc[d]      = fmaf(w0, xl[d],      acc[d]);
        acc[DP + d] = fmaf(w1, xl[DP + d], acc[DP + d]);
    }
}

__global__ void __launch_bounds__(256, 4) k_gat(const float* __restrict__ att,
                                                const float* __restrict__ bias, int slot) {
    __shared__ float sat[12], sb[12], ssum[12], ssq[12];
    int t = threadIdx.x;                 // batch index
    int n = blockIdx.x >> 1;             // dst node
    int k = blockIdx.x & 1;              // head-half (heads 2k, 2k+1)
    if (t < 12) {
        int h = 2 * k + t / DP, d = t % DP;
        sat[t] = (d < Dd) ? att[h * Dd + d]  : 0.f;
        sb[t]  = (d < Dd) ? bias[h * Dd + d] : 0.f;
        ssum[t] = 0.f; ssq[t] = 0.f;
    }
    __syncthreads();

    const float4* XL = g_xl4 + k * 3 * TOTROWS;
    const float4* XR = g_xr4 + k * 3 * TOTROWS;
    float4*       HO = g_h4  + k * 3 * TOTROWS;
    int r = n * Bx + t;

    float xr[12];
    #pragma unroll
    for (int q = 0; q < 3; q++) {
        float4 v = XR[q * TOTROWS + r];
        xr[q*4+0] = v.x; xr[q*4+1] = v.y; xr[q*4+2] = v.z; xr[q*4+3] = v.w;
    }

    float s0 = 0.f, s1 = 0.f, acc[12];
    #pragma unroll
    for (int i = 0; i < 12; i++) acc[i] = 0.f;

    int beg = g_rowptr[n], end = g_rowptr[n + 1];
    int e = beg;
    for (; e + 1 < end; e += 2) {
        int sA = g_csrc[e], sB = g_csrc[e + 1];
        int rA = sA * Bx + t, rB = sB * Bx + t;
        float4 pA[3], pB[3];
        #pragma unroll
        for (int q = 0; q < 3; q++) pA[q] = XL[q * TOTROWS + rA];
        #pragma unroll
        for (int q = 0; q < 3; q++) pB[q] = XL[q * TOTROWS + rB];
        float xlA[12], xlB[12];
        #pragma unroll
        for (int q = 0; q < 3; q++) {
            xlA[q*4+0] = pA[q].x; xlA[q*4+1] = pA[q].y; xlA[q*4+2] = pA[q].z; xlA[q*4+3] = pA[q].w;
            xlB[q*4+0] = pB[q].x; xlB[q*4+1] = pB[q].y; xlB[q*4+2] = pB[q].z; xlB[q*4+3] = pB[q].w;
        }
        gat_edge12(xlA, xr, sat, s0, s1, acc);
        gat_edge12(xlB, xr, sat, s0, s1, acc);
    }
    if (e < end) {
        int sA = g_csrc[e];
        int rA = sA * Bx + t;
        float xlA[12];
        #pragma unroll
        for (int q = 0; q < 3; q++) {
            float4 v = XL[q * TOTROWS + rA];
            xlA[q*4+0] = v.x; xlA[q*4+1] = v.y; xlA[q*4+2] = v.z; xlA[q*4+3] = v.w;
        }
        gat_edge12(xlA, xr, sat, s0, s1, acc);
    }

    float o[12];
    float inv0 = 1.f / s0, inv1 = 1.f / s1;
    #pragma unroll
    for (int d = 0; d < DP; d++) {
        o[d]      = fmaf(acc[d],      inv0, sb[d]);
        o[DP + d] = fmaf(acc[DP + d], inv1, sb[DP + d]);
    }
    #pragma unroll
    for (int q = 0; q < 3; q++)
        HO[q * TOTROWS + r] = make_float4(o[q*4], o[q*4+1], o[q*4+2], o[q*4+3]);

    // fused BN stats (pads are exactly 0, excluded at write)
    float sq[12];
    #pragma unroll
    for (int i = 0; i < 12; i++) sq[i] = o[i] * o[i];
    #pragma unroll
    for (int i = 0; i < 12; i++) {
        for (int off = 16; off; off >>= 1) {
            o[i]  += __shfl_down_sync(0xffffffffu, o[i],  off);
            sq[i] += __shfl_down_sync(0xffffffffu, sq[i], off);
        }
    }
    if ((t & 31) == 0) {
        #pragma unroll
        for (int i = 0; i < 12; i++) {
            atomicAdd(&ssum[i], o[i]);
            atomicAdd(&ssq[i],  sq[i]);
        }
    }
    __syncthreads();
    if (t < 12) {
        int d = t % DP;
        if (d < Dd) {
            int f = (2 * k + t / DP) * Dd + d;
            atomicAdd(&g_bn[slot * 2 * HD + f],      ssum[t]);
            atomicAdd(&g_bn[slot * 2 * HD + HD + f], ssq[t]);
        }
    }
}

// ---------------- mean pool over nodes (layer-1 output): block = batch ----------------
__global__ void k_pool() {
    int b = blockIdx.x, t = threadIdx.x;
    float sum[HDP];
    #pragma unroll
    for (int i = 0; i < HDP; i++) sum[i] = 0.f;
    #pragma unroll
    for (int c = 0; c < 4; c++) {
        int r = (t + c * 256) * Bx + b;
        #pragma unroll
        for (int q = 0; q < NQP; q++) {
            float4 v = g_h4[q * TOTROWS + r];
            sum[q*4+0] += v.x; sum[q*4+1] += v.y;
            sum[q*4+2] += v.z; sum[q*4+3] += v.w;
        }
    }
    #pragma unroll
    for (int i = 0; i < HDP; i++)
        for (int off = 16; off; off >>= 1)
            sum[i] += __shfl_down_sync(0xffffffffu, sum[i], off);
    __shared__ float ssum[HDP];
    if (t < HDP) ssum[t] = 0.f;
    __syncthreads();
    if ((t & 31) == 0) {
        #pragma unroll
        for (int i = 0; i < HDP; i++) atomicAdd(&ssum[i], sum[i]);
    }
    __syncthreads();
    if (t < HD) g_pool[b * HD + t] = ssum[(t / Dd) * DP + (t % Dd)] * (1.f / Nn);
}

// ---------------- head: BN1-affine pool -> agg -> [agg,obs] MLP (4 rows / block) -------
__global__ void k_head(const float* __restrict__ obs,
                       const float* __restrict__ g1, const float* __restrict__ be1,
                       const float* __restrict__ Wagg, const float* __restrict__ bagg,
                       const float* __restrict__ W1, const float* __restrict__ bh1,
                       const float* __restrict__ W2, const float* __restrict__ bh2,
                       const float* __restrict__ Wout, const float* __restrict__ bout,
                       float* __restrict__ out) {
    __shared__ float f[4][AOUTc + OBSc];        // 4 x 1088
    __shared__ float h1s[4][HIDc];
    __shared__ float h2s[4][HIDc / 2];
    __shared__ float sa[HD], sc_[HD];
    int t = threadIdx.x;
    int b0 = blockIdx.x * 4;

    if (t < HD) {
        float mu  = g_bn[2 * HD + t] * (1.f / TOTROWS);
        float var = g_bn[3 * HD + t] * (1.f / TOTROWS) - mu * mu;
        float a = g1[t] * rsqrtf(var + EPSbn);
        sa[t] = a;
        sc_[t] = be1[t] - mu * a;
    }
    __syncthreads();

    if (t < AOUTc) {
        #pragma unroll
        for (int r = 0; r < 4; r++) {
            float acc = bagg[t];
            #pragma unroll
            for (int i = 0; i < HD; i++) {
                float p = fmaf(g_pool[(b0 + r) * HD + i], sa[i], sc_[i]);
                acc = fmaf(p, Wagg[i * AOUTc + t], acc);
            }
            f[r][t] = acc;
        }
    }
    #pragma unroll
    for (int r = 0; r < 4; r++)
        for (int i = t; i < OBSc; i += 256)
            f[r][AOUTc + i] = obs[(b0 + r) * OBSc + i];
    __syncthreads();

    {   // layer 1: 1088 -> 256, tanh
        float a0 = bh1[t], a1 = bh1[t], a2 = bh1[t], a3 = bh1[t];
        #pragma unroll 8
        for (int i = 0; i < AOUTc + OBSc; i++) {
            float w = W1[i * HIDc + t];
            a0 = fmaf(f[0][i], w, a0);
            a1 = fmaf(f[1][i], w, a1);
            a2 = fmaf(f[2][i], w, a2);
            a3 = fmaf(f[3][i], w, a3);
        }
        h1s[0][t] = tanhf(a0); h1s[1][t] = tanhf(a1);
        h1s[2][t] = tanhf(a2); h1s[3][t] = tanhf(a3);
    }
    __syncthreads();

    if (t < HIDc / 2) {   // layer 2: 256 -> 128, tanh
        float acc[4];
        #pragma unroll
        for (int r = 0; r < 4; r++) acc[r] = bh2[t];
        #pragma unroll 8
        for (int i = 0; i < HIDc; i++) {
            float w = W2[i * (HIDc / 2) + t];
            #pragma unroll
            for (int r = 0; r < 4; r++) acc[r] = fmaf(h1s[r][i], w, acc[r]);
        }
        #pragma unroll
        for (int r = 0; r < 4; r++) h2s[r][t] = tanhf(acc[r]);
    }
    __syncthreads();

    if (t < NOUTc) {      // out: 128 -> 64
        float acc[4];
        #pragma unroll
        for (int r = 0; r < 4; r++) acc[r] = bout[t];
        #pragma unroll 8
        for (int i = 0; i < HIDc / 2; i++) {
            float w = Wout[i * NOUTc + t];
            #pragma unroll
            for (int r = 0; r < 4; r++) acc[r] = fmaf(h2s[r][i], w, acc[r]);
        }
        #pragma unroll
        for (int r = 0; r < 4; r++) out[(b0 + r) * NOUTc + t] = acc[r];
    }
}

// ---------------- launch ----------------
extern "C" void kernel_launch(void* const* d_in, const int* in_sizes, int n_in,
                              void* d_out, int out_size) {
    const float* x    = (const float*)d_in[0];
    const float* obs  = (const float*)d_in[1];
    const int*   ei   = (const int*)  d_in[2];
    const float* Wl0  = (const float*)d_in[3];
    const float* Wr0  = (const float*)d_in[4];
    const float* att0 = (const float*)d_in[5];
    const float* b0   = (const float*)d_in[6];
    const float* Wl1  = (const float*)d_in[7];
    const float* Wr1  = (const float*)d_in[8];
    const float* att1 = (const float*)d_in[9];
    const float* b1   = (const float*)d_in[10];
    const float* g0   = (const float*)d_in[11];
    const float* be0  = (const float*)d_in[12];
    const float* g1   = (const float*)d_in[13];
    const float* be1  = (const float*)d_in[14];
    const float* Wagg = (const float*)d_in[15];
    const float* bagg = (const float*)d_in[16];
    const float* W1   = (const float*)d_in[17];
    const float* bh1  = (const float*)d_in[18];
    const float* W2   = (const float*)d_in[19];
    const float* bh2  = (const float*)d_in[20];
    const float* Wout = (const float*)d_in[21];
    const float* bout = (const float*)d_in[22];
    float* out = (float*)d_out;

    // 4th launch = ncu capture slot = k_gat layer 0
    k_csr1<<<1, 1024>>>(ei);
    k_scatter<<<CHK, 1024>>>(ei);
    k_lin0<<<TOTROWS / 256, 256>>>(x, Wl0, Wr0);
    k_gat<<<Nn * 2, 256>>>(att0, b0, 0);      // <- profiled launch
    k_lin1<<<TOTROWS / 256, 256>>>(Wl1, Wr1, g0, be0);
    k_gat<<<Nn * 2, 256>>>(att1, b1, 1);
    k_pool<<<Bx, 256>>>();
    k_head<<<Bx / 4, 256>>>(obs, g1, be1, Wagg, bagg, W1, bh1, W2, bh2, Wout, bout, out);
}

// round 6
// speedup vs baseline: 1.4492x; 1.4492x over previous
#include <cuda_runtime.h>
#include <math.h>

#define Bx 256
#define Nn 1024
#define Ee 8192
#define FINc 8
#define Hh 4
#define Dd 5
#define HD 20
#define ES (Ee + Nn)          // 9216 edges incl. self loops
#define CHK (ES / 1024)       // 9 chunks of 1024 edges
#define AOUTc 64
#define OBSc 1024
#define HIDc 256
#define NOUTc 64
#define NEGs 0.2f
#define EPSbn 1e-5f
#define TOTROWS (Bx * Nn)     // 262144
#define NQ 5                  // HD/4 float4 quads per row

// ---------------- device scratch: SoA float4 planes, r = n*Bx + b ----------------
__device__ float4 g_xl4[NQ * TOTROWS];
__device__ float4 g_xr4[NQ * TOTROWS];
__device__ float4 g_h4[NQ * TOTROWS];
__device__ float g_pool[Bx * HD];
__device__ float g_bn[4 * HD];       // [sum0, sumsq0, sum1, sumsq1]
__device__ int   g_rowptr[Nn + 1];
__device__ int   g_cnt[CHK * Nn];
__device__ int   g_csrc[ES];

// ---------------- helpers ----------------
__device__ __forceinline__ void edge_sd(const int* ei, int e, int& s, int& d) {
    if (e < Ee) { s = ei[e]; d = ei[Ee + e]; }
    else        { s = e - Ee; d = s; }       // appended self loops
}

// FMA-pipe exp: avoids MUFU (the measured bottleneck in k_gat).
// exp(x) = 2^(x*log2e); round via magic constant, degree-5 Taylor for 2^f, |f|<=0.5.
// Rel err ~2.4e-6. Valid for |x| < ~80 (covers attention logits by a wide margin).
__device__ __forceinline__ float fexp(float x) {
    float y = fmaf(x, 1.44269504f, 12582912.0f);     // 1.5*2^23: RN-to-int in mantissa
    int   ii = __float_as_int(y) - 0x4B400000;       // integer part (two's complement)
    float i  = y - 12582912.0f;
    float f  = fmaf(x, 1.44269504f, -i);             // frac in [-0.5, 0.5]
    float p  =            0.0013333558f;
    p = fmaf(p, f, 0.0096181291f);
    p = fmaf(p, f, 0.0555041087f);
    p = fmaf(p, f, 0.2402265069f);
    p = fmaf(p, f, 0.6931471806f);
    p = fmaf(p, f, 1.0f);
    return p * __int_as_float((ii + 127) << 23);
}

// ---------------- fused CSR stage 1: zero + per-chunk hist + scan (1 block, 1024 thr) ----
__global__ void k_csr1(const int* __restrict__ ei) {
    __shared__ int run[Nn];
    __shared__ int sc[Nn];
    int t = threadIdx.x;
    if (t < 4 * HD) g_bn[t] = 0.f;
    run[t] = 0;
    __syncthreads();
    #pragma unroll
    for (int c = 0; c < CHK; c++) {
        g_cnt[c * Nn + t] = run[t];          // chunk-exclusive running count
        __syncthreads();
        int e = c * 1024 + t;
        int s, d; edge_sd(ei, e, s, d);
        atomicAdd(&run[d], 1);
        __syncthreads();
    }
    int tot = run[t];
    sc[t] = tot;
    __syncthreads();
    for (int off = 1; off < Nn; off <<= 1) { // Hillis-Steele inclusive scan
        int v = (t >= off) ? sc[t - off] : 0;
        __syncthreads();
        sc[t] += v;
        __syncthreads();
    }
    g_rowptr[t] = sc[t] - tot;               // exclusive
    if (t == Nn - 1) g_rowptr[Nn] = sc[t];
}

// ---------------- CSR scatter: match_any + warp-serialized cursors (deterministic) ----
__global__ void k_scatter(const int* __restrict__ ei) {
    __shared__ int cur[Nn];
    int t = threadIdx.x;                      // 1024
    int chunk = blockIdx.x;                   // 9
    cur[t] = g_rowptr[t] + g_cnt[chunk * Nn + t];
    __syncthreads();
    int e = chunk * 1024 + t;
    int s, d; edge_sd(ei, e, s, d);
    int w = t >> 5, lane = t & 31;
    #pragma unroll 1
    for (int ww = 0; ww < 32; ww++) {         // warps take turns -> stable order
        if (w == ww) {
            unsigned mask = __match_any_sync(0xffffffffu, d);
            int leader = __ffs(mask) - 1;
            int rank = __popc(mask & ((1u << lane) - 1u));
            int base = 0;
            if (lane == leader) base = atomicAdd(&cur[d], __popc(mask));
            base = __shfl_sync(0xffffffffu, base, leader);
            g_csrc[base + rank] = s;
        }
        __syncthreads();
    }
}

// ---------------- layer-0 linear: xl = x@Wl0, xr = x@Wr0  (write planes) ----------------
__global__ void k_lin0(const float* __restrict__ x,
                       const float* __restrict__ Wl, const float* __restrict__ Wr) {
    __shared__ float sl[FINc * HD], sr[FINc * HD];
    int t = threadIdx.x;
    if (t < FINc * HD) { sl[t] = Wl[t]; sr[t] = Wr[t]; }
    __syncthreads();
    int r = blockIdx.x * blockDim.x + t;     // r = n*Bx + b
    int n = r >> 8;
    int b = r & (Bx - 1);
    const float4* xp = (const float4*)(x + (b * Nn + n) * FINc);
    float4 v0 = xp[0], v1 = xp[1];
    float xv[FINc] = {v0.x, v0.y, v0.z, v0.w, v1.x, v1.y, v1.z, v1.w};
    float al[HD], ar[HD];
    #pragma unroll
    for (int o = 0; o < HD; o++) {
        float a = 0.f, c = 0.f;
        #pragma unroll
        for (int i = 0; i < FINc; i++) {
            a = fmaf(xv[i], sl[i * HD + o], a);
            c = fmaf(xv[i], sr[i * HD + o], c);
        }
        al[o] = a; ar[o] = c;
    }
    #pragma unroll
    for (int q = 0; q < NQ; q++) {
        g_xl4[q * TOTROWS + r] = make_float4(al[q*4], al[q*4+1], al[q*4+2], al[q*4+3]);
        g_xr4[q * TOTROWS + r] = make_float4(ar[q*4], ar[q*4+1], ar[q*4+2], ar[q*4+3]);
    }
}

// ---------------- layer-1 linear with fused BN0 affine (planes in/out) ----------------
__global__ void k_lin1(const float* __restrict__ Wl, const float* __restrict__ Wr,
                       const float* __restrict__ gam, const float* __restrict__ bet) {
    __shared__ float sl[HD * HD], sr[HD * HD], sa[HD], sc_[HD];
    int t = threadIdx.x;
    if (t < HD) {
        float mu  = g_bn[t] * (1.f / TOTROWS);
        float var = g_bn[HD + t] * (1.f / TOTROWS) - mu * mu;
        float a = gam[t] * rsqrtf(var + EPSbn);
        sa[t] = a;
        sc_[t] = bet[t] - mu * a;
    }
    for (int i = t; i < HD * HD; i += blockDim.x) { sl[i] = Wl[i]; sr[i] = Wr[i]; }
    __syncthreads();
    int r = blockIdx.x * blockDim.x + t;
    float v[HD];
    #pragma unroll
    for (int q = 0; q < NQ; q++) {
        float4 h4 = g_h4[q * TOTROWS + r];
        v[q*4+0] = h4.x; v[q*4+1] = h4.y; v[q*4+2] = h4.z; v[q*4+3] = h4.w;
    }
    #pragma unroll
    for (int i = 0; i < HD; i++) v[i] = fmaf(v[i], sa[i], sc_[i]);
    float al[HD], ar[HD];
    #pragma unroll
    for (int o = 0; o < HD; o++) {
        float a = 0.f, c = 0.f;
        #pragma unroll
        for (int i = 0; i < HD; i++) {
            a = fmaf(v[i], sl[i * HD + o], a);
            c = fmaf(v[i], sr[i * HD + o], c);
        }
        al[o] = a; ar[o] = c;
    }
    #pragma unroll
    for (int q = 0; q < NQ; q++) {
        g_xl4[q * TOTROWS + r] = make_float4(al[q*4], al[q*4+1], al[q*4+2], al[q*4+3]);
        g_xr4[q * TOTROWS + r] = make_float4(ar[q*4], ar[q*4+1], ar[q*4+2], ar[q*4+3]);
    }
}

// ---------------- GATv2 aggregation: block = dst node, thread = batch ----------------
// 2-edge unrolled main loop; exp on the FMA pipe (MUFU was the binding pipe).
__device__ __forceinline__ void gat_edge(const float xl[HD], const float xr[HD],
                                         const float* sat, float s[Hh], float acc[HD]) {
    #pragma unroll
    for (int h = 0; h < Hh; h++) {
        float e = 0.f;
        #pragma unroll
        for (int d = 0; d < Dd; d++) {
            float v = xl[h * Dd + d] + xr[h * Dd + d];
            v = fmaxf(v, NEGs * v);            // leaky_relu(0.2)
            e = fmaf(v, sat[h * Dd + d], e);
        }
        float w = fexp(e);                     // FMA-pipe exp; |e| = O(1)
        s[h] += w;
        #pragma unroll
        for (int d = 0; d < Dd; d++)
            acc[h * Dd + d] = fmaf(w, xl[h * Dd + d], acc[h * Dd + d]);
    }
}

__global__ void __launch_bounds__(256) k_gat(const float* __restrict__ att,
                                             const float* __restrict__ bias) {
    __shared__ float sat[HD], sb[HD];
    int t = threadIdx.x;                 // batch index
    int n = blockIdx.x;                  // dst node
    if (t < HD) { sat[t] = att[t]; sb[t] = bias[t]; }
    __syncthreads();

    int r = n * Bx + t;
    float xr[HD];
    #pragma unroll
    for (int q = 0; q < NQ; q++) {
        float4 v = g_xr4[q * TOTROWS + r];
        xr[q*4+0] = v.x; xr[q*4+1] = v.y; xr[q*4+2] = v.z; xr[q*4+3] = v.w;
    }

    float s[Hh], acc[HD];
    #pragma unroll
    for (int h = 0; h < Hh; h++) s[h] = 0.f;
    #pragma unroll
    for (int i = 0; i < HD; i++) acc[i] = 0.f;

    int beg = g_rowptr[n], end = g_rowptr[n + 1];
    int k = beg;
    for (; k + 1 < end; k += 2) {
        int s0 = g_csrc[k], s1 = g_csrc[k + 1];
        int r0 = s0 * Bx + t, r1 = s1 * Bx + t;
        float4 p0[NQ], p1[NQ];
        #pragma unroll
        for (int q = 0; q < NQ; q++) p0[q] = g_xl4[q * TOTROWS + r0];
        #pragma unroll
        for (int q = 0; q < NQ; q++) p1[q] = g_xl4[q * TOTROWS + r1];
        float xl0[HD], xl1[HD];
        #pragma unroll
        for (int q = 0; q < NQ; q++) {
            xl0[q*4+0] = p0[q].x; xl0[q*4+1] = p0[q].y; xl0[q*4+2] = p0[q].z; xl0[q*4+3] = p0[q].w;
            xl1[q*4+0] = p1[q].x; xl1[q*4+1] = p1[q].y; xl1[q*4+2] = p1[q].z; xl1[q*4+3] = p1[q].w;
        }
        gat_edge(xl0, xr, sat, s, acc);
        gat_edge(xl1, xr, sat, s, acc);
    }
    if (k < end) {
        int s0 = g_csrc[k];
        int r0 = s0 * Bx + t;
        float xl0[HD];
        #pragma unroll
        for (int q = 0; q < NQ; q++) {
            float4 v = g_xl4[q * TOTROWS + r0];
            xl0[q*4+0] = v.x; xl0[q*4+1] = v.y; xl0[q*4+2] = v.z; xl0[q*4+3] = v.w;
        }
        gat_edge(xl0, xr, sat, s, acc);
    }

    float o[HD];
    #pragma unroll
    for (int h = 0; h < Hh; h++) {
        float inv = 1.f / s[h];
        #pragma unroll
        for (int d = 0; d < Dd; d++)
            o[h * Dd + d] = fmaf(acc[h * Dd + d], inv, sb[h * Dd + d]);
    }
    #pragma unroll
    for (int q = 0; q < NQ; q++)
        g_h4[q * TOTROWS + r] = make_float4(o[q*4], o[q*4+1], o[q*4+2], o[q*4+3]);
}

// ---------------- BN stats over all rows (coalesced plane reads) ----------------
__global__ void k_stats(int slot) {
    int tid = blockIdx.x * blockDim.x + threadIdx.x;   // 512*256 threads, 2 rows each
    float sum[HD], sq[HD];
    #pragma unroll
    for (int i = 0; i < HD; i++) { sum[i] = 0.f; sq[i] = 0.f; }
    #pragma unroll
    for (int c = 0; c < 2; c++) {
        int r = tid + c * (512 * 256);
        #pragma unroll
        for (int q = 0; q < NQ; q++) {
            float4 v = g_h4[q * TOTROWS + r];
            sum[q*4+0] += v.x; sq[q*4+0] += v.x * v.x;
            sum[q*4+1] += v.y; sq[q*4+1] += v.y * v.y;
            sum[q*4+2] += v.z; sq[q*4+2] += v.z * v.z;
            sum[q*4+3] += v.w; sq[q*4+3] += v.w * v.w;
        }
    }
    #pragma unroll
    for (int i = 0; i < HD; i++) {
        for (int off = 16; off; off >>= 1) {
            sum[i] += __shfl_down_sync(0xffffffffu, sum[i], off);
            sq[i]  += __shfl_down_sync(0xffffffffu, sq[i],  off);
        }
    }
    __shared__ float ssum[HD], ssq[HD];
    int t = threadIdx.x;
    if (t < HD) { ssum[t] = 0.f; ssq[t] = 0.f; }
    __syncthreads();
    if ((t & 31) == 0) {
        #pragma unroll
        for (int i = 0; i < HD; i++) {
            atomicAdd(&ssum[i], sum[i]);
            atomicAdd(&ssq[i],  sq[i]);
        }
    }
    __syncthreads();
    if (t < HD) {
        atomicAdd(&g_bn[slot * 2 * HD + t],      ssum[t]);
        atomicAdd(&g_bn[slot * 2 * HD + HD + t], ssq[t]);
    }
}

// ---------------- mean pool over nodes (layer-1 output): block = batch ----------------
__global__ void k_pool() {
    int b = blockIdx.x, t = threadIdx.x;
    float sum[HD];
    #pragma unroll
    for (int i = 0; i < HD; i++) sum[i] = 0.f;
    #pragma unroll
    for (int c = 0; c < 4; c++) {
        int r = (t + c * 256) * Bx + b;
        #pragma unroll
        for (int q = 0; q < NQ; q++) {
            float4 v = g_h4[q * TOTROWS + r];
            sum[q*4+0] += v.x; sum[q*4+1] += v.y;
            sum[q*4+2] += v.z; sum[q*4+3] += v.w;
        }
    }
    #pragma unroll
    for (int i = 0; i < HD; i++)
        for (int off = 16; off; off >>= 1)
            sum[i] += __shfl_down_sync(0xffffffffu, sum[i], off);
    __shared__ float ssum[HD];
    if (t < HD) ssum[t] = 0.f;
    __syncthreads();
    if ((t & 31) == 0) {
        #pragma unroll
        for (int i = 0; i < HD; i++) atomicAdd(&ssum[i], sum[i]);
    }
    __syncthreads();
    if (t < HD) g_pool[b * HD + t] = ssum[t] * (1.f / Nn);
}

// ---------------- head: BN1-affine pool -> agg -> [agg,obs] MLP (2 rows / block) ----------------
__global__ void k_head(const float* __restrict__ obs,
                       const float* __restrict__ g1, const float* __restrict__ be1,
                       const float* __restrict__ Wagg, const float* __restrict__ bagg,
                       const float* __restrict__ W1, const float* __restrict__ bh1,
                       const float* __restrict__ W2, const float* __restrict__ bh2,
                       const float* __restrict__ Wout, const float* __restrict__ bout,
                       float* __restrict__ out) {
    __shared__ float f[2][AOUTc + OBSc];        // 2 x 1088
    __shared__ float h1s[2][HIDc];
    __shared__ float h2s[2][HIDc / 2];
    __shared__ float sa[HD], sc_[HD];
    int t = threadIdx.x;
    int b0 = blockIdx.x * 2;

    if (t < HD) {
        float mu  = g_bn[2 * HD + t] * (1.f / TOTROWS);
        float var = g_bn[3 * HD + t] * (1.f / TOTROWS) - mu * mu;
        float a = g1[t] * rsqrtf(var + EPSbn);
        sa[t] = a;
        sc_[t] = be1[t] - mu * a;
    }
    __syncthreads();

    if (t < AOUTc) {
        #pragma unroll
        for (int r = 0; r < 2; r++) {
            float acc = bagg[t];
            #pragma unroll
            for (int i = 0; i < HD; i++) {
                float p = fmaf(g_pool[(b0 + r) * HD + i], sa[i], sc_[i]);
                acc = fmaf(p, Wagg[i * AOUTc + t], acc);
            }
            f[r][t] = acc;
        }
    }
    #pragma unroll
    for (int r = 0; r < 2; r++)
        for (int i = t; i < OBSc; i += 256)
            f[r][AOUTc + i] = obs[(b0 + r) * OBSc + i];
    __syncthreads();

    {   // layer 1: 1088 -> 256, tanh
        float a0 = bh1[t], a1 = bh1[t];
        #pragma unroll 8
        for (int i = 0; i < AOUTc + OBSc; i++) {
            float w = W1[i * HIDc + t];
            a0 = fmaf(f[0][i], w, a0);
            a1 = fmaf(f[1][i], w, a1);
        }
        h1s[0][t] = tanhf(a0); h1s[1][t] = tanhf(a1);
    }
    __syncthreads();

    if (t < HIDc / 2) {   // layer 2: 256 -> 128, tanh
        float acc[2];
        #pragma unroll
        for (int r = 0; r < 2; r++) acc[r] = bh2[t];
        #pragma unroll 8
        for (int i = 0; i < HIDc; i++) {
            float w = W2[i * (HIDc / 2) + t];
            #pragma unroll
            for (int r = 0; r < 2; r++) acc[r] = fmaf(h1s[r][i], w, acc[r]);
        }
        #pragma unroll
        for (int r = 0; r < 2; r++) h2s[r][t] = tanhf(acc[r]);
    }
    __syncthreads();

    if (t < NOUTc) {      // out: 128 -> 64
        float acc[2];
        #pragma unroll
        for (int r = 0; r < 2; r++) acc[r] = bout[t];
        #pragma unroll 8
        for (int i = 0; i < HIDc / 2; i++) {
            float w = Wout[i * NOUTc + t];
            #pragma unroll
            for (int r = 0; r < 2; r++) acc[r] = fmaf(h2s[r][i], w, acc[r]);
        }
        #pragma unroll
        for (int r = 0; r < 2; r++) out[(b0 + r) * NOUTc + t] = acc[r];
    }
}

// ---------------- launch ----------------
extern "C" void kernel_launch(void* const* d_in, const int* in_sizes, int n_in,
                              void* d_out, int out_size) {
    const float* x    = (const float*)d_in[0];
    const float* obs  = (const float*)d_in[1];
    const int*   ei   = (const int*)  d_in[2];
    const float* Wl0  = (const float*)d_in[3];
    const float* Wr0  = (const float*)d_in[4];
    const float* att0 = (const float*)d_in[5];
    const float* b0   = (const float*)d_in[6];
    const float* Wl1  = (const float*)d_in[7];
    const float* Wr1  = (const float*)d_in[8];
    const float* att1 = (const float*)d_in[9];
    const float* b1   = (const float*)d_in[10];
    const float* g0   = (const float*)d_in[11];
    const float* be0  = (const float*)d_in[12];
    const float* g1   = (const float*)d_in[13];
    const float* be1  = (const float*)d_in[14];
    const float* Wagg = (const float*)d_in[15];
    const float* bagg = (const float*)d_in[16];
    const float* W1   = (const float*)d_in[17];
    const float* bh1  = (const float*)d_in[18];
    const float* W2   = (const float*)d_in[19];
    const float* bh2  = (const float*)d_in[20];
    const float* Wout = (const float*)d_in[21];
    const float* bout = (const float*)d_in[22];
    float* out = (float*)d_out;

    // 4th launch = ncu capture slot = k_gat layer 0
    k_csr1<<<1, 1024>>>(ei);
    k_scatter<<<CHK, 1024>>>(ei);
    k_lin0<<<TOTROWS / 256, 256>>>(x, Wl0, Wr0);
    k_gat<<<Nn, 256>>>(att0, b0);            // <- profiled launch
    k_stats<<<512, 256>>>(0);

    k_lin1<<<TOTROWS / 256, 256>>>(Wl1, Wr1, g0, be0);
    k_gat<<<Nn, 256>>>(att1, b1);
    k_stats<<<512, 256>>>(1);

    k_pool<<<Bx, 256>>>();
    k_head<<<Bx / 2, 256>>>(obs, g1, be1, Wagg, bagg, W1, bh1, W2, bh2, Wout, bout, out);
}